// round 2
// baseline (speedup 1.0000x reference)
#include <cuda_runtime.h>
#include <math.h>

#define EPSV 1e-8f

namespace {
constexpr int B  = 32;
constexpr int S  = 64;
constexpr int H  = 200;
constexpr int L  = 20;
constexpr int HP = 201;      // padded smem row stride (201 % 32 = 9, conflict-free)
constexpr int CS = 400;      // con_* inner stride (2*H)
constexpr int MV = 160;      // 8*L output columns
constexpr int PSIZE = B * S * MV;   // elements in mv_p (== mv_h)
}

// ---------------- scratch (device globals; no allocation allowed) -------------
__device__ float g_att[2 * B * S * S];        // [dir][b][p][q]
__device__ float g_rowsum[2 * B * S];         // sum_q att[p][q]
__device__ float g_colsum[2 * B * S];         // sum_p att[p][q]
__device__ float g_amean_h[2 * B * S * H];    // indexed by p
__device__ float g_amax_h [2 * B * S * H];
__device__ float g_amean_p[2 * B * S * H];    // indexed by q
__device__ float g_amax_p [2 * B * S * H];

// ============================ Kernel A1: attention ===========================
// grid (B, 2), 256 threads. Computes cosine attention matrix + row/col sums.
__global__ void __launch_bounds__(256)
attn_kernel(const float* __restrict__ con_p,
            const float* __restrict__ con_h) {
    extern __shared__ float sm[];
    float* P   = sm;                  // S*HP
    float* Hm  = P  + S * HP;         // S*HP
    float* att = Hm + S * HP;         // S*(S+1)
    float* np  = att + S * (S + 1);   // S
    float* nh  = np + S;              // S

    const int b = blockIdx.x, dir = blockIdx.y;
    const int tid = threadIdx.x;
    const float* pbase = con_p + (size_t)b * S * CS + dir * H;
    const float* hbase = con_h + (size_t)b * S * CS + dir * H;

    for (int i = tid; i < S * H; i += blockDim.x) {
        int s = i / H, h = i % H;
        P [s * HP + h] = pbase[s * CS + h];
        Hm[s * HP + h] = hbase[s * CS + h];
    }
    __syncthreads();

    if (tid < S) {
        float acc = 0.f;
        #pragma unroll 4
        for (int h = 0; h < H; h++) { float v = P[tid * HP + h]; acc += v * v; }
        np[tid] = sqrtf(acc);
    } else if (tid < 2 * S) {
        int q = tid - S;
        float acc = 0.f;
        #pragma unroll 4
        for (int h = 0; h < H; h++) { float v = Hm[q * HP + h]; acc += v * v; }
        nh[q] = sqrtf(acc);
    }
    __syncthreads();

    for (int it = tid; it < S * S; it += blockDim.x) {
        int p = it >> 6, q = it & 63;
        float dot = 0.f;
        #pragma unroll 4
        for (int h = 0; h < H; h++) dot += P[p * HP + h] * Hm[q * HP + h];
        float d = np[p] * nh[q];
        att[p * (S + 1) + q] = dot / (d > EPSV ? d : EPSV);
    }
    __syncthreads();

    float* gatt = g_att + (size_t)(dir * B + b) * S * S;
    for (int it = tid; it < S * S; it += blockDim.x) {
        int p = it >> 6, q = it & 63;
        gatt[it] = att[p * (S + 1) + q];
    }
    if (tid < S) {
        float rs = 0.f;
        for (int q = 0; q < S; q++) rs += att[tid * (S + 1) + q];
        g_rowsum[(dir * B + b) * S + tid] = rs;
    } else if (tid < 2 * S) {
        int q = tid - S;
        float cs = 0.f;
        for (int p = 0; p < S; p++) cs += att[p * (S + 1) + q];
        g_colsum[(dir * B + b) * S + q] = cs;
    }
}

// ===================== Kernel A2: att mean/max vectors =======================
// grid (B, 2, 8): z = side*4 + hchunk (4 chunks of 50 h each).
// side 0: out indexed by p (uses H rows, rowsum); side 1: indexed by q (P rows, colsum).
__global__ void __launch_bounds__(256)
attderiv_kernel(const float* __restrict__ con_p,
                const float* __restrict__ con_h) {
    extern __shared__ float sm[];
    float* att  = sm;                   // S*(S+1)
    float* V    = att + S * (S + 1);    // S*52
    float* dsum = V + S * 52;           // S

    const int b = blockIdx.x, dir = blockIdx.y;
    const int side = blockIdx.z >> 2;
    const int h0 = (blockIdx.z & 3) * 50;
    const int tid = threadIdx.x;

    const float* gatt = g_att + (size_t)(dir * B + b) * S * S;
    for (int i = tid; i < S * S; i += blockDim.x)
        att[(i >> 6) * (S + 1) + (i & 63)] = gatt[i];

    const float* src = (side == 0 ? con_h : con_p) + (size_t)b * S * CS + dir * H + h0;
    for (int i = tid; i < S * 50; i += blockDim.x) {
        int s = i / 50, hh = i % 50;
        V[s * 52 + hh] = src[s * CS + hh];
    }
    if (tid < S)
        dsum[tid] = (side == 0 ? g_rowsum : g_colsum)[(dir * B + b) * S + tid];
    __syncthreads();

    float* gmean = (side == 0 ? g_amean_h : g_amean_p) + (size_t)(dir * B + b) * S * H + h0;
    float* gmax  = (side == 0 ? g_amax_h  : g_amax_p ) + (size_t)(dir * B + b) * S * H + h0;

    for (int i = tid; i < S * 50; i += blockDim.x) {
        int o = i / 50, hh = i % 50;
        float ssum = 0.f, smax = -INFINITY;
        if (side == 0) {
            #pragma unroll 4
            for (int q = 0; q < S; q++) {
                float v = att[o * (S + 1) + q] * V[q * 52 + hh];
                ssum += v; smax = fmaxf(smax, v);
            }
        } else {
            #pragma unroll 4
            for (int p = 0; p < S; p++) {
                float v = att[p * (S + 1) + o] * V[p * 52 + hh];
                ssum += v; smax = fmaxf(smax, v);
            }
        }
        float d = dsum[o];
        gmean[o * H + hh] = ssum / (d > EPSV ? d : EPSV);   // _dsmall: where(d>EPS,d,EPS)
        gmax [o * H + hh] = smax;
    }
}

// ====================== Kernel B: 12 fused mp_match ops ======================
// grid (B, 12). op: side = op/6 (0: mv_p, 1: mv_h); r = op%6; kind = r/2
// (0 full, 1 att_mean, 2 att_max); dir = r%2.
__global__ void __launch_bounds__(256)
match_kernel(const float* __restrict__ con_p,
             const float* __restrict__ con_h,
             const float* __restrict__ w1, const float* __restrict__ w2,
             const float* __restrict__ w5, const float* __restrict__ w6,
             const float* __restrict__ w7, const float* __restrict__ w8,
             float* __restrict__ out) {
    extern __shared__ float sm[];
    float* V1 = sm;              // S*HP
    float* V2 = V1 + S * HP;     // S*HP (kind 0 uses row 0 only)
    float* W  = V2 + S * HP;     // L*HP

    const int b = blockIdx.x, op = blockIdx.y;
    const int side = op / 6;
    const int r = op % 6;
    const int kind = r >> 1;
    const int dir = r & 1;
    const int tid = threadIdx.x;

    // v1: rows of con_p (side 0) or con_h (side 1), selected direction half.
    const float* v1 = (side == 0 ? con_p : con_h) + (size_t)b * S * CS + dir * H;
    for (int i = tid; i < S * H; i += blockDim.x) {
        int s = i / H, h = i % H;
        V1[s * HP + h] = v1[s * CS + h];
    }

    // v2
    if (kind == 0) {
        const float* v2 = (side == 0 ? con_h : con_p)
                        + (size_t)b * S * CS + (dir == 0 ? (S - 1) : 0) * CS + dir * H;
        for (int h = tid; h < H; h += blockDim.x) V2[h] = v2[h];
    } else {
        const float* v2 = (kind == 1 ? (side == 0 ? g_amean_h : g_amean_p)
                                     : (side == 0 ? g_amax_h  : g_amax_p))
                        + (size_t)(dir * B + b) * S * H;
        for (int i = tid; i < S * H; i += blockDim.x) {
            int s = i / H, h = i % H;
            V2[s * HP + h] = v2[s * H + h];
        }
    }

    // weight matrix for this op
    const float* w = (kind == 0 ? (dir == 0 ? w1 : w2)
                   : kind == 1 ? (dir == 0 ? w5 : w6)
                               : (dir == 0 ? w7 : w8));
    for (int i = tid; i < L * H; i += blockDim.x) {
        int l = i / H, h = i % H;
        W[l * HP + h] = w[i];
    }
    __syncthreads();

    const int col = (kind == 0 ? 0 : kind == 1 ? 40 : 60) + dir * 80;
    float* obase = out + (size_t)side * PSIZE + (size_t)b * S * MV;

    for (int it = tid; it < S * L; it += blockDim.x) {
        int s = it / L, l = it % L;
        const float* v1r = V1 + s * HP;
        const float* v2r = V2 + (kind == 0 ? 0 : s * HP);
        const float* wr  = W  + l * HP;
        float dot = 0.f, na = 0.f, nb = 0.f;
        #pragma unroll 4
        for (int h = 0; h < H; h++) {
            float wv = wr[h];
            float a = v1r[h] * wv;
            float bb = v2r[h] * wv;
            dot += a * bb; na += a * a; nb += bb * bb;
        }
        float d = sqrtf(na) * sqrtf(nb);
        obase[s * MV + col + l] = dot / fmaxf(d, EPSV);
    }
}

// ================= Kernel C: pairwise mp + max reductions ====================
// grid (B, L, 2) = 1280 blocks, 256 threads (16x16, 4x4 register tile).
__global__ void __launch_bounds__(256)
pairwise_kernel(const float* __restrict__ con_p,
                const float* __restrict__ con_h,
                const float* __restrict__ w3,
                const float* __restrict__ w4,
                float* __restrict__ out) {
    extern __shared__ float sm[];
    float* A    = sm;                 // S*HP  (p * w_l)
    float* Bm   = A + S * HP;         // S*HP  (h * w_l)
    float* na   = Bm + S * HP;        // S
    float* nb   = na + S;             // S
    float* redP = nb + S;             // S*16
    float* redQ = redP + S * 16;      // S*16
    float* wsh  = redQ + S * 16;      // H

    const int b = blockIdx.x, l = blockIdx.y, dir = blockIdx.z;
    const int tid = threadIdx.x;

    const float* w = (dir == 0 ? w3 : w4) + l * H;
    for (int h = tid; h < H; h += blockDim.x) wsh[h] = w[h];
    __syncthreads();

    const float* pb = con_p + (size_t)b * S * CS + dir * H;
    const float* hb = con_h + (size_t)b * S * CS + dir * H;
    for (int i = tid; i < S * H; i += blockDim.x) {
        int s = i / H, h = i % H;
        float wv = wsh[h];
        A [s * HP + h] = pb[s * CS + h] * wv;
        Bm[s * HP + h] = hb[s * CS + h] * wv;
    }
    __syncthreads();

    if (tid < S) {
        float acc = 0.f;
        #pragma unroll 4
        for (int h = 0; h < H; h++) { float v = A[tid * HP + h]; acc += v * v; }
        na[tid] = sqrtf(acc);
    } else if (tid < 2 * S) {
        int q = tid - S;
        float acc = 0.f;
        #pragma unroll 4
        for (int h = 0; h < H; h++) { float v = Bm[q * HP + h]; acc += v * v; }
        nb[q] = sqrtf(acc);
    }
    __syncthreads();

    const int tx = tid & 15, ty = tid >> 4;
    float acc[4][4];
    #pragma unroll
    for (int i = 0; i < 4; i++)
        #pragma unroll
        for (int j = 0; j < 4; j++) acc[i][j] = 0.f;

    #pragma unroll 2
    for (int h = 0; h < H; h++) {
        float pa[4], pbv[4];
        #pragma unroll
        for (int i = 0; i < 4; i++) pa[i] = A[(ty + 16 * i) * HP + h];
        #pragma unroll
        for (int j = 0; j < 4; j++) pbv[j] = Bm[(tx + 16 * j) * HP + h];
        #pragma unroll
        for (int i = 0; i < 4; i++)
            #pragma unroll
            for (int j = 0; j < 4; j++) acc[i][j] += pa[i] * pbv[j];
    }

    float pmax[4] = {-INFINITY, -INFINITY, -INFINITY, -INFINITY};
    float qmax[4] = {-INFINITY, -INFINITY, -INFINITY, -INFINITY};
    #pragma unroll
    for (int i = 0; i < 4; i++) {
        int p = ty + 16 * i;
        #pragma unroll
        for (int j = 0; j < 4; j++) {
            int q = tx + 16 * j;
            float d = na[p] * nb[q];
            float c = acc[i][j] / (d > EPSV ? d : EPSV);   // _dsmall (d >= 0 here)
            pmax[i] = fmaxf(pmax[i], c);
            qmax[j] = fmaxf(qmax[j], c);
        }
    }
    #pragma unroll
    for (int i = 0; i < 4; i++) redP[(ty + 16 * i) * 16 + tx] = pmax[i];
    #pragma unroll
    for (int j = 0; j < 4; j++) redQ[(tx + 16 * j) * 16 + ty] = qmax[j];
    __syncthreads();

    const int colbase = (dir == 0 ? 20 : 100) + l;
    if (tid < S) {
        float m = -INFINITY;
        #pragma unroll
        for (int k = 0; k < 16; k++) m = fmaxf(m, redP[tid * 16 + k]);
        out[((size_t)b * S + tid) * MV + colbase] = m;                      // mv_p
    } else if (tid < 2 * S) {
        int q = tid - S;
        float m = -INFINITY;
        #pragma unroll
        for (int k = 0; k < 16; k++) m = fmaxf(m, redQ[q * 16 + k]);
        out[(size_t)PSIZE + ((size_t)b * S + q) * MV + colbase] = m;        // mv_h
    }
}

// ================================ launcher ===================================
extern "C" void kernel_launch(void* const* d_in, const int* in_sizes, int n_in,
                              void* d_out, int out_size) {
    const float* con_p = (const float*)d_in[0];
    const float* con_h = (const float*)d_in[1];
    const float* w1 = (const float*)d_in[2];
    const float* w2 = (const float*)d_in[3];
    const float* w3 = (const float*)d_in[4];
    const float* w4 = (const float*)d_in[5];
    const float* w5 = (const float*)d_in[6];
    const float* w6 = (const float*)d_in[7];
    const float* w7 = (const float*)d_in[8];
    const float* w8 = (const float*)d_in[9];
    float* out = (float*)d_out;

    constexpr size_t SM_A1 = (size_t)(2 * S * HP + S * (S + 1) + 2 * S) * sizeof(float);
    constexpr size_t SM_A2 = (size_t)(S * (S + 1) + S * 52 + S) * sizeof(float);
    constexpr size_t SM_B  = (size_t)(2 * S * HP + L * HP) * sizeof(float);
    constexpr size_t SM_C  = (size_t)(2 * S * HP + 2 * S + 2 * S * 16 + H) * sizeof(float);

    // One-time attribute setup: runs on the first (correctness) call, before
    // graph capture, so the captured graph contains only kernel launches.
    static bool attrs_set = false;
    if (!attrs_set) {
        cudaFuncSetAttribute(attn_kernel,     cudaFuncAttributeMaxDynamicSharedMemorySize, (int)SM_A1);
        cudaFuncSetAttribute(match_kernel,    cudaFuncAttributeMaxDynamicSharedMemorySize, (int)SM_B);
        cudaFuncSetAttribute(pairwise_kernel, cudaFuncAttributeMaxDynamicSharedMemorySize, (int)SM_C);
        attrs_set = true;
    }

    attn_kernel<<<dim3(B, 2), 256, SM_A1>>>(con_p, con_h);
    attderiv_kernel<<<dim3(B, 2, 8), 256, SM_A2>>>(con_p, con_h);
    match_kernel<<<dim3(B, 12), 256, SM_B>>>(con_p, con_h, w1, w2, w5, w6, w7, w8, out);
    pairwise_kernel<<<dim3(B, L, 2), 256, SM_C>>>(con_p, con_h, w3, w4, out);
}

// round 3
// speedup vs baseline: 1.7781x; 1.7781x over previous
#include <cuda_runtime.h>
#include <math.h>

#define EPSV 1e-8f

namespace {
constexpr int B  = 32;
constexpr int S  = 64;
constexpr int H  = 200;
constexpr int L  = 20;
constexpr int HP = 201;      // smem row stride: 201 % 32 = 9 -> conflict-free columns
constexpr int CS = 400;      // con_* inner stride (2*H)
constexpr int MV = 160;      // 8*L output columns
constexpr int PSIZE = B * S * MV;
constexpr int VST = 104;     // attderiv V stride (100 hh padded, 16B-aligned)
}

// ---------------- scratch (device globals; no allocation allowed) -------------
__device__ float g_att[2 * B * S * S];        // [dir][b][p][q]
__device__ float g_rowsum[2 * B * S];
__device__ float g_colsum[2 * B * S];
__device__ float g_amean_h[2 * B * S * H];    // indexed by p
__device__ float g_amax_h [2 * B * S * H];
__device__ float g_amean_p[2 * B * S * H];    // indexed by q
__device__ float g_amax_p [2 * B * S * H];

// ============================ Kernel A1: attention ===========================
// grid (B, 2), 128 threads. 8x4 register tile over the 64x64 cosine matrix.
__global__ void __launch_bounds__(128)
attn_kernel(const float* __restrict__ con_p,
            const float* __restrict__ con_h) {
    extern __shared__ float sm[];
    float* P     = sm;                     // S*HP
    float* Hm    = P  + S * HP;            // S*HP
    float* np    = Hm + S * HP;            // S
    float* nh    = np + S;                 // S
    float* redRS = nh + S;                 // S*16
    float* redCS = redRS + S * 16;         // S*8

    const int b = blockIdx.x, dir = blockIdx.y;
    const int tid = threadIdx.x;
    const float* pbase = con_p + (size_t)b * S * CS + dir * H;
    const float* hbase = con_h + (size_t)b * S * CS + dir * H;

    for (int i = tid; i < S * H; i += 128) {
        int s = i / H, h = i % H;
        P [s * HP + h] = pbase[s * CS + h];
        Hm[s * HP + h] = hbase[s * CS + h];
    }
    __syncthreads();

    if (tid < S) {
        float acc = 0.f;
        #pragma unroll 4
        for (int h = 0; h < H; h++) { float v = P[tid * HP + h]; acc += v * v; }
        np[tid] = sqrtf(acc);
    } else {
        int q = tid - S;
        float acc = 0.f;
        #pragma unroll 4
        for (int h = 0; h < H; h++) { float v = Hm[q * HP + h]; acc += v * v; }
        nh[q] = sqrtf(acc);
    }
    __syncthreads();

    const int tx = tid & 15, ty = tid >> 4;   // ty 0..7
    float acc[8][4];
    #pragma unroll
    for (int i = 0; i < 8; i++)
        #pragma unroll
        for (int j = 0; j < 4; j++) acc[i][j] = 0.f;

    #pragma unroll 2
    for (int h = 0; h < H; h++) {
        float pa[8], pbv[4];
        #pragma unroll
        for (int i = 0; i < 8; i++) pa[i] = P[(ty + 8 * i) * HP + h];
        #pragma unroll
        for (int j = 0; j < 4; j++) pbv[j] = Hm[(tx + 16 * j) * HP + h];
        #pragma unroll
        for (int i = 0; i < 8; i++)
            #pragma unroll
            for (int j = 0; j < 4; j++) acc[i][j] += pa[i] * pbv[j];
    }

    float* gatt = g_att + (size_t)(dir * B + b) * S * S;
    float rsum[8], csum[4];
    #pragma unroll
    for (int i = 0; i < 8; i++) rsum[i] = 0.f;
    #pragma unroll
    for (int j = 0; j < 4; j++) csum[j] = 0.f;

    #pragma unroll
    for (int i = 0; i < 8; i++) {
        int p = ty + 8 * i;
        #pragma unroll
        for (int j = 0; j < 4; j++) {
            int q = tx + 16 * j;
            float d = np[p] * nh[q];
            float c = acc[i][j] / (d > EPSV ? d : EPSV);
            gatt[p * S + q] = c;
            rsum[i] += c;
            csum[j] += c;
        }
    }
    #pragma unroll
    for (int i = 0; i < 8; i++) redRS[(ty + 8 * i) * 16 + tx] = rsum[i];
    #pragma unroll
    for (int j = 0; j < 4; j++) redCS[(tx + 16 * j) * 8 + ty] = csum[j];
    __syncthreads();

    if (tid < S) {
        float s0 = 0.f;
        #pragma unroll
        for (int k = 0; k < 16; k++) s0 += redRS[tid * 16 + k];
        g_rowsum[(dir * B + b) * S + tid] = s0;
    } else {
        int q = tid - S;
        float s0 = 0.f;
        #pragma unroll
        for (int k = 0; k < 8; k++) s0 += redCS[q * 8 + k];
        g_colsum[(dir * B + b) * S + q] = s0;
    }
}

// ===================== Kernel A2: att mean/max vectors =======================
// grid (B, 2, 4): z = side*2 + chunk (2 chunks of 100 hh). 256 threads.
// Per-thread 8(o) x 4(hh) tile -> 200 tiles, threads 200..255 idle in main loop.
__global__ void __launch_bounds__(256)
attderiv_kernel(const float* __restrict__ con_p,
                const float* __restrict__ con_h) {
    extern __shared__ float sm[];
    float* att  = sm;                   // S*65
    float* V    = att + S * 65;         // S*VST
    float* dsum = V + S * VST;          // S

    const int b = blockIdx.x, dir = blockIdx.y;
    const int side = blockIdx.z >> 1;
    const int ck = blockIdx.z & 1;
    const int h0 = ck * 100;
    const int tid = threadIdx.x;

    const float* gatt = g_att + (size_t)(dir * B + b) * S * S;
    for (int i = tid; i < S * S; i += 256)
        att[(i >> 6) * 65 + (i & 63)] = gatt[i];

    const float* src = (side == 0 ? con_h : con_p) + (size_t)b * S * CS + dir * H + h0;
    // 64 rows x 100 cols, float4 loads/stores
    for (int i4 = tid; i4 < S * 25; i4 += 256) {
        int s = i4 / 25, c4 = i4 % 25;
        float4 v = *reinterpret_cast<const float4*>(src + s * CS + c4 * 4);
        *reinterpret_cast<float4*>(V + s * VST + c4 * 4) = v;
    }
    if (tid < S)
        dsum[tid] = (side == 0 ? g_rowsum : g_colsum)[(dir * B + b) * S + tid];
    __syncthreads();

    float* gmean = (side == 0 ? g_amean_h : g_amean_p) + (size_t)(dir * B + b) * S * H + h0;
    float* gmax  = (side == 0 ? g_amax_h  : g_amax_p ) + (size_t)(dir * B + b) * S * H + h0;

    if (tid < 200) {
        const int oi = tid / 25, hi = tid % 25;     // oi 0..7 -> 8 o's, hi -> 4 hh's
        const int o0 = oi * 8, hb = hi * 4;

        float ss[8][4], sx[8][4];
        #pragma unroll
        for (int io = 0; io < 8; io++)
            #pragma unroll
            for (int k = 0; k < 4; k++) { ss[io][k] = 0.f; sx[io][k] = -INFINITY; }

        for (int q = 0; q < S; q++) {
            float av[8];
            if (side == 0) {
                #pragma unroll
                for (int io = 0; io < 8; io++) av[io] = att[(o0 + io) * 65 + q];
            } else {
                #pragma unroll
                for (int io = 0; io < 8; io++) av[io] = att[q * 65 + (o0 + io)];
            }
            float4 v = *reinterpret_cast<const float4*>(V + q * VST + hb);
            float vv[4] = {v.x, v.y, v.z, v.w};
            #pragma unroll
            for (int io = 0; io < 8; io++)
                #pragma unroll
                for (int k = 0; k < 4; k++) {
                    float t = av[io] * vv[k];
                    ss[io][k] += t;
                    sx[io][k] = fmaxf(sx[io][k], t);
                }
        }
        #pragma unroll
        for (int io = 0; io < 8; io++) {
            float d = dsum[o0 + io];
            float inv = 1.f / (d > EPSV ? d : EPSV);
            float4 m4, x4;
            m4.x = ss[io][0] * inv; m4.y = ss[io][1] * inv;
            m4.z = ss[io][2] * inv; m4.w = ss[io][3] * inv;
            x4.x = sx[io][0]; x4.y = sx[io][1]; x4.z = sx[io][2]; x4.w = sx[io][3];
            *reinterpret_cast<float4*>(gmean + (o0 + io) * H + hb) = m4;
            *reinterpret_cast<float4*>(gmax  + (o0 + io) * H + hb) = x4;
        }
    }
}

// ====================== Kernel B: 12 fused mp_match ops ======================
// grid (B, 12), 128 threads. dot = sum v1*v2*w^2 ; na^2 = sum v1^2*w^2 ; etc.
// Per-thread tile: 2 s x 5 l.
__global__ void __launch_bounds__(128)
match_kernel(const float* __restrict__ con_p,
             const float* __restrict__ con_h,
             const float* __restrict__ w1, const float* __restrict__ w2,
             const float* __restrict__ w5, const float* __restrict__ w6,
             const float* __restrict__ w7, const float* __restrict__ w8,
             float* __restrict__ out) {
    extern __shared__ float sm[];
    float* V1 = sm;              // S*HP
    float* V2 = V1 + S * HP;     // S*HP (kind 0 uses row 0 only)
    float* W2 = V2 + S * HP;     // L*HP (w squared)

    const int b = blockIdx.x, op = blockIdx.y;
    const int side = op / 6;
    const int r = op % 6;
    const int kind = r >> 1;
    const int dir = r & 1;
    const int tid = threadIdx.x;

    const float* v1 = (side == 0 ? con_p : con_h) + (size_t)b * S * CS + dir * H;
    for (int i = tid; i < S * H; i += 128) {
        int s = i / H, h = i % H;
        V1[s * HP + h] = v1[s * CS + h];
    }

    if (kind == 0) {
        const float* v2 = (side == 0 ? con_h : con_p)
                        + (size_t)b * S * CS + (dir == 0 ? (S - 1) : 0) * CS + dir * H;
        for (int h = tid; h < H; h += 128) V2[h] = v2[h];
    } else {
        const float* v2 = (kind == 1 ? (side == 0 ? g_amean_h : g_amean_p)
                                     : (side == 0 ? g_amax_h  : g_amax_p))
                        + (size_t)(dir * B + b) * S * H;
        for (int i = tid; i < S * H; i += 128) {
            int s = i / H, h = i % H;
            V2[s * HP + h] = v2[i];
        }
    }

    const float* w = (kind == 0 ? (dir == 0 ? w1 : w2)
                   : kind == 1 ? (dir == 0 ? w5 : w6)
                               : (dir == 0 ? w7 : w8));
    for (int i = tid; i < L * H; i += 128) {
        int l = i / H, h = i % H;
        float wv = w[i];
        W2[l * HP + h] = wv * wv;
    }
    __syncthreads();

    const int tx = tid & 3;        // l group: l = tx*5 + il
    const int ty = tid >> 2;       // s group: s = ty*2 + is

    const float* v1p0 = V1 + (ty * 2 + 0) * HP;
    const float* v1p1 = V1 + (ty * 2 + 1) * HP;
    const float* v2p0 = (kind == 0) ? V2 : V2 + (ty * 2 + 0) * HP;
    const float* v2p1 = (kind == 0) ? V2 : V2 + (ty * 2 + 1) * HP;
    const float* wp[5];
    #pragma unroll
    for (int il = 0; il < 5; il++) wp[il] = W2 + (tx * 5 + il) * HP;

    float dacc[2][5], naa[2][5], nbb[2][5];
    #pragma unroll
    for (int is = 0; is < 2; is++)
        #pragma unroll
        for (int il = 0; il < 5; il++) { dacc[is][il] = 0.f; naa[is][il] = 0.f; nbb[is][il] = 0.f; }

    #pragma unroll 2
    for (int h = 0; h < H; h++) {
        float a0 = v1p0[h], a1 = v1p1[h];
        float b0 = v2p0[h], b1 = v2p1[h];
        float u1_0 = a0 * b0, u2_0 = a0 * a0, u3_0 = b0 * b0;
        float u1_1 = a1 * b1, u2_1 = a1 * a1, u3_1 = b1 * b1;
        #pragma unroll
        for (int il = 0; il < 5; il++) {
            float w2v = wp[il][h];
            dacc[0][il] += u1_0 * w2v;  naa[0][il] += u2_0 * w2v;  nbb[0][il] += u3_0 * w2v;
            dacc[1][il] += u1_1 * w2v;  naa[1][il] += u2_1 * w2v;  nbb[1][il] += u3_1 * w2v;
        }
    }

    const int col = (kind == 0 ? 0 : kind == 1 ? 40 : 60) + dir * 80;
    float* obase = out + (size_t)side * PSIZE + (size_t)b * S * MV;
    #pragma unroll
    for (int is = 0; is < 2; is++)
        #pragma unroll
        for (int il = 0; il < 5; il++) {
            float d = sqrtf(naa[is][il]) * sqrtf(nbb[is][il]);
            obase[(ty * 2 + is) * MV + col + (tx * 5 + il)] =
                dacc[is][il] / fmaxf(d, EPSV);
        }
}

// ================= Kernel C: pairwise mp + max reductions ====================
// grid (B, L, 2), 128 threads, 8x4 register tile.
__global__ void __launch_bounds__(128)
pairwise_kernel(const float* __restrict__ con_p,
                const float* __restrict__ con_h,
                const float* __restrict__ w3,
                const float* __restrict__ w4,
                float* __restrict__ out) {
    extern __shared__ float sm[];
    float* A    = sm;                 // S*HP  (p * w_l)
    float* Bm   = A + S * HP;         // S*HP  (h * w_l)
    float* na   = Bm + S * HP;        // S
    float* nb   = na + S;             // S
    float* wsh  = nb + S;             // H
    float* redP = wsh + H;            // S*16
    float* redQ = redP + S * 16;      // S*8

    const int b = blockIdx.x, l = blockIdx.y, dir = blockIdx.z;
    const int tid = threadIdx.x;

    const float* w = (dir == 0 ? w3 : w4) + l * H;
    for (int h = tid; h < H; h += 128) wsh[h] = w[h];
    __syncthreads();

    const float* pb = con_p + (size_t)b * S * CS + dir * H;
    const float* hb = con_h + (size_t)b * S * CS + dir * H;
    for (int i = tid; i < S * H; i += 128) {
        int s = i / H, h = i % H;
        float wv = wsh[h];
        A [s * HP + h] = pb[s * CS + h] * wv;
        Bm[s * HP + h] = hb[s * CS + h] * wv;
    }
    __syncthreads();

    if (tid < S) {
        float acc = 0.f;
        #pragma unroll 4
        for (int h = 0; h < H; h++) { float v = A[tid * HP + h]; acc += v * v; }
        na[tid] = sqrtf(acc);
    } else {
        int q = tid - S;
        float acc = 0.f;
        #pragma unroll 4
        for (int h = 0; h < H; h++) { float v = Bm[q * HP + h]; acc += v * v; }
        nb[q] = sqrtf(acc);
    }
    __syncthreads();

    const int tx = tid & 15, ty = tid >> 4;   // ty 0..7
    float acc[8][4];
    #pragma unroll
    for (int i = 0; i < 8; i++)
        #pragma unroll
        for (int j = 0; j < 4; j++) acc[i][j] = 0.f;

    #pragma unroll 2
    for (int h = 0; h < H; h++) {
        float pa[8], pbv[4];
        #pragma unroll
        for (int i = 0; i < 8; i++) pa[i] = A[(ty + 8 * i) * HP + h];
        #pragma unroll
        for (int j = 0; j < 4; j++) pbv[j] = Bm[(tx + 16 * j) * HP + h];
        #pragma unroll
        for (int i = 0; i < 8; i++)
            #pragma unroll
            for (int j = 0; j < 4; j++) acc[i][j] += pa[i] * pbv[j];
    }

    float pmax[8], qmax[4];
    #pragma unroll
    for (int i = 0; i < 8; i++) pmax[i] = -INFINITY;
    #pragma unroll
    for (int j = 0; j < 4; j++) qmax[j] = -INFINITY;

    #pragma unroll
    for (int i = 0; i < 8; i++) {
        int p = ty + 8 * i;
        #pragma unroll
        for (int j = 0; j < 4; j++) {
            int q = tx + 16 * j;
            float d = na[p] * nb[q];
            float c = acc[i][j] / (d > EPSV ? d : EPSV);
            pmax[i] = fmaxf(pmax[i], c);
            qmax[j] = fmaxf(qmax[j], c);
        }
    }
    #pragma unroll
    for (int i = 0; i < 8; i++) redP[(ty + 8 * i) * 16 + tx] = pmax[i];
    #pragma unroll
    for (int j = 0; j < 4; j++) redQ[(tx + 16 * j) * 8 + ty] = qmax[j];
    __syncthreads();

    const int colbase = (dir == 0 ? 20 : 100) + l;
    if (tid < S) {
        float m = -INFINITY;
        #pragma unroll
        for (int k = 0; k < 16; k++) m = fmaxf(m, redP[tid * 16 + k]);
        out[((size_t)b * S + tid) * MV + colbase] = m;                      // mv_p
    } else {
        int q = tid - S;
        float m = -INFINITY;
        #pragma unroll
        for (int k = 0; k < 8; k++) m = fmaxf(m, redQ[q * 8 + k]);
        out[(size_t)PSIZE + ((size_t)b * S + q) * MV + colbase] = m;        // mv_h
    }
}

// ================================ launcher ===================================
extern "C" void kernel_launch(void* const* d_in, const int* in_sizes, int n_in,
                              void* d_out, int out_size) {
    const float* con_p = (const float*)d_in[0];
    const float* con_h = (const float*)d_in[1];
    const float* w1 = (const float*)d_in[2];
    const float* w2 = (const float*)d_in[3];
    const float* w3 = (const float*)d_in[4];
    const float* w4 = (const float*)d_in[5];
    const float* w5 = (const float*)d_in[6];
    const float* w6 = (const float*)d_in[7];
    const float* w7 = (const float*)d_in[8];
    const float* w8 = (const float*)d_in[9];
    float* out = (float*)d_out;

    constexpr size_t SM_A1 = (size_t)(2 * S * HP + 2 * S + S * 16 + S * 8) * sizeof(float);
    constexpr size_t SM_A2 = (size_t)(S * 65 + S * VST + S) * sizeof(float);
    constexpr size_t SM_B  = (size_t)(2 * S * HP + L * HP) * sizeof(float);
    constexpr size_t SM_C  = (size_t)(2 * S * HP + 2 * S + H + S * 16 + S * 8) * sizeof(float);

    static bool attrs_set = false;
    if (!attrs_set) {
        cudaFuncSetAttribute(attn_kernel,     cudaFuncAttributeMaxDynamicSharedMemorySize, (int)SM_A1);
        cudaFuncSetAttribute(attderiv_kernel, cudaFuncAttributeMaxDynamicSharedMemorySize, (int)SM_A2);
        cudaFuncSetAttribute(match_kernel,    cudaFuncAttributeMaxDynamicSharedMemorySize, (int)SM_B);
        cudaFuncSetAttribute(pairwise_kernel, cudaFuncAttributeMaxDynamicSharedMemorySize, (int)SM_C);
        attrs_set = true;
    }

    attn_kernel<<<dim3(B, 2), 128, SM_A1>>>(con_p, con_h);
    attderiv_kernel<<<dim3(B, 2, 4), 256, SM_A2>>>(con_p, con_h);
    match_kernel<<<dim3(B, 12), 128, SM_B>>>(con_p, con_h, w1, w2, w5, w6, w7, w8, out);
    pairwise_kernel<<<dim3(B, L, 2), 128, SM_C>>>(con_p, con_h, w3, w4, out);
}

// round 4
// speedup vs baseline: 1.7921x; 1.0079x over previous
#include <cuda_runtime.h>
#include <math.h>

#define EPSV 1e-8f

typedef unsigned long long ull;

namespace {
constexpr int B  = 32;
constexpr int S  = 64;
constexpr int H  = 200;
constexpr int L  = 20;
constexpr int HP = 202;      // smem row stride: even (8B-aligned rows), 202%32=10 -> 16 rows conflict-free
constexpr int CS = 400;      // con_* inner stride (2*H)
constexpr int MV = 160;      // 8*L output columns
constexpr int PSIZE = B * S * MV;
constexpr int AST = 66;      // attderiv att/attT row stride
constexpr int VST = 104;     // attderiv V stride (100 hh padded, 16B-aligned)
constexpr int WST = 200;     // match W2 row stride
}

// packed f32x2 helpers (ptxas never auto-fuses these)
__device__ __forceinline__ void fma2(ull& d, ull a, ull b) {
    asm("fma.rn.f32x2 %0, %1, %2, %0;" : "+l"(d) : "l"(a), "l"(b));
}
__device__ __forceinline__ ull mul2(ull a, ull b) {
    ull r; asm("mul.rn.f32x2 %0, %1, %2;" : "=l"(r) : "l"(a), "l"(b)); return r;
}
__device__ __forceinline__ float red2(ull v) {
    float2 f = *reinterpret_cast<float2*>(&v);
    return f.x + f.y;
}

// ---------------- scratch (device globals; no allocation allowed) -------------
__device__ __align__(16) float g_att[2 * B * S * S];
__device__ __align__(16) float g_rowsum[2 * B * S];
__device__ __align__(16) float g_colsum[2 * B * S];
__device__ __align__(16) float g_amean_h[2 * B * S * H];
__device__ __align__(16) float g_amax_h [2 * B * S * H];
__device__ __align__(16) float g_amean_p[2 * B * S * H];
__device__ __align__(16) float g_amax_p [2 * B * S * H];

// ============================ Kernel A1: attention ===========================
// grid (B, 2), 128 threads. 8x4 register tile, f32x2-packed along h.
__global__ void __launch_bounds__(128)
attn_kernel(const float* __restrict__ con_p,
            const float* __restrict__ con_h) {
    extern __shared__ float sm[];
    float* P     = sm;                     // S*HP
    float* Hm    = P  + S * HP;            // S*HP
    float* np    = Hm + S * HP;            // S
    float* nh    = np + S;                 // S
    float* redRS = nh + S;                 // S*16
    float* redCS = redRS + S * 16;         // S*8

    const int b = blockIdx.x, dir = blockIdx.y;
    const int tid = threadIdx.x;
    const float* pbase = con_p + (size_t)b * S * CS + dir * H;
    const float* hbase = con_h + (size_t)b * S * CS + dir * H;

    for (int i2 = tid; i2 < S * 100; i2 += 128) {
        int s = i2 / 100, h2 = i2 % 100;
        *reinterpret_cast<float2*>(P  + s * HP + 2 * h2) =
            *reinterpret_cast<const float2*>(pbase + s * CS + 2 * h2);
        *reinterpret_cast<float2*>(Hm + s * HP + 2 * h2) =
            *reinterpret_cast<const float2*>(hbase + s * CS + 2 * h2);
    }
    __syncthreads();

    if (tid < S) {
        float acc = 0.f;
        #pragma unroll 4
        for (int k = 0; k < 100; k++) {
            float2 v = *reinterpret_cast<const float2*>(P + tid * HP + 2 * k);
            acc += v.x * v.x + v.y * v.y;
        }
        np[tid] = sqrtf(acc);
    } else {
        int q = tid - S;
        float acc = 0.f;
        #pragma unroll 4
        for (int k = 0; k < 100; k++) {
            float2 v = *reinterpret_cast<const float2*>(Hm + q * HP + 2 * k);
            acc += v.x * v.x + v.y * v.y;
        }
        nh[q] = sqrtf(acc);
    }
    __syncthreads();

    const int tx = tid & 15, ty = tid >> 4;
    const ull* Ap[8]; const ull* Bp[4];
    #pragma unroll
    for (int i = 0; i < 8; i++) Ap[i] = reinterpret_cast<const ull*>(P  + (ty + 8 * i) * HP);
    #pragma unroll
    for (int j = 0; j < 4; j++) Bp[j] = reinterpret_cast<const ull*>(Hm + (tx + 16 * j) * HP);

    ull acc2[8][4];
    #pragma unroll
    for (int i = 0; i < 8; i++)
        #pragma unroll
        for (int j = 0; j < 4; j++) acc2[i][j] = 0ull;

    ull ca[8], cb[4];
    #pragma unroll
    for (int i = 0; i < 8; i++) ca[i] = Ap[i][0];
    #pragma unroll
    for (int j = 0; j < 4; j++) cb[j] = Bp[j][0];

    #pragma unroll 2
    for (int h2 = 1; h2 < 100; h2++) {
        ull ta[8], tb[4];
        #pragma unroll
        for (int i = 0; i < 8; i++) ta[i] = Ap[i][h2];
        #pragma unroll
        for (int j = 0; j < 4; j++) tb[j] = Bp[j][h2];
        #pragma unroll
        for (int i = 0; i < 8; i++)
            #pragma unroll
            for (int j = 0; j < 4; j++) fma2(acc2[i][j], ca[i], cb[j]);
        #pragma unroll
        for (int i = 0; i < 8; i++) ca[i] = ta[i];
        #pragma unroll
        for (int j = 0; j < 4; j++) cb[j] = tb[j];
    }
    #pragma unroll
    for (int i = 0; i < 8; i++)
        #pragma unroll
        for (int j = 0; j < 4; j++) fma2(acc2[i][j], ca[i], cb[j]);

    float* gatt = g_att + (size_t)(dir * B + b) * S * S;
    float rsum[8], csum[4];
    #pragma unroll
    for (int i = 0; i < 8; i++) rsum[i] = 0.f;
    #pragma unroll
    for (int j = 0; j < 4; j++) csum[j] = 0.f;

    #pragma unroll
    for (int i = 0; i < 8; i++) {
        int p = ty + 8 * i;
        #pragma unroll
        for (int j = 0; j < 4; j++) {
            int q = tx + 16 * j;
            float d = np[p] * nh[q];
            float c = red2(acc2[i][j]) / (d > EPSV ? d : EPSV);
            gatt[p * S + q] = c;
            rsum[i] += c;
            csum[j] += c;
        }
    }
    #pragma unroll
    for (int i = 0; i < 8; i++) redRS[(ty + 8 * i) * 16 + tx] = rsum[i];
    #pragma unroll
    for (int j = 0; j < 4; j++) redCS[(tx + 16 * j) * 8 + ty] = csum[j];
    __syncthreads();

    if (tid < S) {
        float s0 = 0.f;
        #pragma unroll
        for (int k = 0; k < 16; k++) s0 += redRS[tid * 16 + k];
        g_rowsum[(dir * B + b) * S + tid] = s0;
    } else {
        int q = tid - S;
        float s0 = 0.f;
        #pragma unroll
        for (int k = 0; k < 8; k++) s0 += redCS[q * 8 + k];
        g_colsum[(dir * B + b) * S + q] = s0;
    }
}

// ===================== Kernel A2: att mean/max vectors =======================
// grid (B, 2, 4): z = side*2 + chunk. 256 threads. attT copy -> contiguous-q
// float2 loads on both sides; per-thread 8(o) x 4(hh) tile, q unrolled by 2.
__global__ void __launch_bounds__(256)
attderiv_kernel(const float* __restrict__ con_p,
                const float* __restrict__ con_h) {
    extern __shared__ float sm[];
    float* att  = sm;                    // S*AST
    float* attT = att + S * AST;         // S*AST
    float* V    = attT + S * AST;        // S*VST
    float* dsum = V + S * VST;           // S

    const int b = blockIdx.x, dir = blockIdx.y;
    const int side = blockIdx.z >> 1;
    const int ck = blockIdx.z & 1;
    const int h0 = ck * 100;
    const int tid = threadIdx.x;

    const float* gatt = g_att + (size_t)(dir * B + b) * S * S;
    for (int i = tid; i < S * S; i += 256) {
        int p = i >> 6, q = i & 63;
        float v = gatt[i];
        att [p * AST + q] = v;
        attT[q * AST + p] = v;
    }

    const float* src = (side == 0 ? con_h : con_p) + (size_t)b * S * CS + dir * H + h0;
    for (int i4 = tid; i4 < S * 25; i4 += 256) {
        int s = i4 / 25, c4 = i4 % 25;
        *reinterpret_cast<float4*>(V + s * VST + c4 * 4) =
            *reinterpret_cast<const float4*>(src + s * CS + c4 * 4);
    }
    if (tid < S)
        dsum[tid] = (side == 0 ? g_rowsum : g_colsum)[(dir * B + b) * S + tid];
    __syncthreads();

    float* gmean = (side == 0 ? g_amean_h : g_amean_p) + (size_t)(dir * B + b) * S * H + h0;
    float* gmax  = (side == 0 ? g_amax_h  : g_amax_p ) + (size_t)(dir * B + b) * S * H + h0;

    if (tid < 200) {
        const int oi = tid / 25, hi = tid % 25;
        const int o0 = oi * 8, hb = hi * 4;
        const float* M = (side == 0) ? att : attT;   // M[o][q]

        float ss[8][4], sx[8][4];
        #pragma unroll
        for (int io = 0; io < 8; io++)
            #pragma unroll
            for (int k = 0; k < 4; k++) { ss[io][k] = 0.f; sx[io][k] = -INFINITY; }

        for (int q2 = 0; q2 < 32; q2++) {
            const int q = 2 * q2;
            float2 av[8];
            #pragma unroll
            for (int io = 0; io < 8; io++)
                av[io] = *reinterpret_cast<const float2*>(M + (o0 + io) * AST + q);
            float4 v0 = *reinterpret_cast<const float4*>(V + q * VST + hb);
            float4 v1 = *reinterpret_cast<const float4*>(V + (q + 1) * VST + hb);
            float vv0[4] = {v0.x, v0.y, v0.z, v0.w};
            float vv1[4] = {v1.x, v1.y, v1.z, v1.w};
            #pragma unroll
            for (int io = 0; io < 8; io++) {
                float ax = av[io].x, ay = av[io].y;
                #pragma unroll
                for (int k = 0; k < 4; k++) {
                    float t0 = ax * vv0[k];
                    float t1 = ay * vv1[k];
                    ss[io][k] += t0 + t1;
                    sx[io][k] = fmaxf(sx[io][k], fmaxf(t0, t1));
                }
            }
        }
        #pragma unroll
        for (int io = 0; io < 8; io++) {
            float d = dsum[o0 + io];
            float inv = 1.f / (d > EPSV ? d : EPSV);
            float4 m4, x4;
            m4.x = ss[io][0] * inv; m4.y = ss[io][1] * inv;
            m4.z = ss[io][2] * inv; m4.w = ss[io][3] * inv;
            x4.x = sx[io][0]; x4.y = sx[io][1]; x4.z = sx[io][2]; x4.w = sx[io][3];
            *reinterpret_cast<float4*>(gmean + (o0 + io) * H + hb) = m4;
            *reinterpret_cast<float4*>(gmax  + (o0 + io) * H + hb) = x4;
        }
    }
}

// ====================== Kernel B: 12 fused mp_match ops ======================
// grid (B, 12, 2), 128 threads. Block handles 32 s x 20 l of one op.
// dot = sum v1*v2*w^2 (etc.) packed along h via f32x2.
__global__ void __launch_bounds__(128)
match_kernel(const float* __restrict__ con_p,
             const float* __restrict__ con_h,
             const float* __restrict__ w1, const float* __restrict__ w2,
             const float* __restrict__ w5, const float* __restrict__ w6,
             const float* __restrict__ w7, const float* __restrict__ w8,
             float* __restrict__ out) {
    extern __shared__ float sm[];
    float* V1 = sm;                 // 32*HP
    float* V2 = V1 + 32 * HP;       // 32*HP (kind 0 uses row 0 only)
    float* W2 = V2 + 32 * HP;       // L*WST

    const int b = blockIdx.x, op = blockIdx.y, shalf = blockIdx.z;
    const int side = op / 6;
    const int r = op % 6;
    const int kind = r >> 1;
    const int dir = r & 1;
    const int tid = threadIdx.x;
    const int s0 = shalf * 32;

    const float* v1 = (side == 0 ? con_p : con_h) + (size_t)b * S * CS + dir * H;
    for (int i2 = tid; i2 < 32 * 100; i2 += 128) {
        int s = i2 / 100, h2 = i2 % 100;
        *reinterpret_cast<float2*>(V1 + s * HP + 2 * h2) =
            *reinterpret_cast<const float2*>(v1 + (s0 + s) * CS + 2 * h2);
    }

    if (kind == 0) {
        const float* v2 = (side == 0 ? con_h : con_p)
                        + (size_t)b * S * CS + (dir == 0 ? (S - 1) : 0) * CS + dir * H;
        for (int h2 = tid; h2 < 100; h2 += 128)
            *reinterpret_cast<float2*>(V2 + 2 * h2) =
                *reinterpret_cast<const float2*>(v2 + 2 * h2);
    } else {
        const float* v2 = (kind == 1 ? (side == 0 ? g_amean_h : g_amean_p)
                                     : (side == 0 ? g_amax_h  : g_amax_p))
                        + (size_t)(dir * B + b) * S * H;
        for (int i2 = tid; i2 < 32 * 100; i2 += 128) {
            int s = i2 / 100, h2 = i2 % 100;
            *reinterpret_cast<float2*>(V2 + s * HP + 2 * h2) =
                *reinterpret_cast<const float2*>(v2 + (s0 + s) * H + 2 * h2);
        }
    }

    const float* w = (kind == 0 ? (dir == 0 ? w1 : w2)
                   : kind == 1 ? (dir == 0 ? w5 : w6)
                               : (dir == 0 ? w7 : w8));
    for (int i2 = tid; i2 < L * 100; i2 += 128) {
        int l = i2 / 100, h2 = i2 % 100;
        float2 wv = *reinterpret_cast<const float2*>(w + l * H + 2 * h2);
        float2 sq; sq.x = wv.x * wv.x; sq.y = wv.y * wv.y;
        *reinterpret_cast<float2*>(W2 + l * WST + 2 * h2) = sq;
    }
    __syncthreads();

    const int tx = tid & 3;        // l group: l = tx*5 + il
    const int ty = tid >> 2;       // s = s0 + ty

    const ull* Ap = reinterpret_cast<const ull*>(V1 + ty * HP);
    const ull* Bp = reinterpret_cast<const ull*>((kind == 0) ? V2 : V2 + ty * HP);
    const ull* Wp[5];
    #pragma unroll
    for (int il = 0; il < 5; il++)
        Wp[il] = reinterpret_cast<const ull*>(W2 + (tx * 5 + il) * WST);

    ull dacc[5], naa[5], nbb[5];
    #pragma unroll
    for (int il = 0; il < 5; il++) { dacc[il] = 0ull; naa[il] = 0ull; nbb[il] = 0ull; }

    #pragma unroll 2
    for (int h2 = 0; h2 < 100; h2++) {
        ull a = Ap[h2], bb = Bp[h2];
        ull u1 = mul2(a, bb), u2 = mul2(a, a), u3 = mul2(bb, bb);
        #pragma unroll
        for (int il = 0; il < 5; il++) {
            ull wv = Wp[il][h2];
            fma2(dacc[il], u1, wv);
            fma2(naa[il], u2, wv);
            fma2(nbb[il], u3, wv);
        }
    }

    const int col = (kind == 0 ? 0 : kind == 1 ? 40 : 60) + dir * 80;
    float* obase = out + (size_t)side * PSIZE + (size_t)b * S * MV;
    #pragma unroll
    for (int il = 0; il < 5; il++) {
        float d = sqrtf(red2(naa[il])) * sqrtf(red2(nbb[il]));
        obase[(s0 + ty) * MV + col + (tx * 5 + il)] = red2(dacc[il]) / fmaxf(d, EPSV);
    }
}

// ================= Kernel C: pairwise mp + max reductions ====================
// grid (B, L, 2), 128 threads, 8x4 tile, f32x2-packed, prefetched.
__global__ void __launch_bounds__(128)
pairwise_kernel(const float* __restrict__ con_p,
                const float* __restrict__ con_h,
                const float* __restrict__ w3,
                const float* __restrict__ w4,
                float* __restrict__ out) {
    extern __shared__ float sm[];
    float* A    = sm;                 // S*HP  (p * w_l)
    float* Bm   = A + S * HP;         // S*HP  (h * w_l)
    float* na   = Bm + S * HP;        // S
    float* nb   = na + S;             // S
    float* wsh  = nb + S;             // H
    float* redP = wsh + H;            // S*16
    float* redQ = redP + S * 16;      // S*8

    const int b = blockIdx.x, l = blockIdx.y, dir = blockIdx.z;
    const int tid = threadIdx.x;

    const float* w = (dir == 0 ? w3 : w4) + l * H;
    for (int h2 = tid; h2 < 100; h2 += 128)
        *reinterpret_cast<float2*>(wsh + 2 * h2) =
            *reinterpret_cast<const float2*>(w + 2 * h2);
    __syncthreads();

    const float* pb = con_p + (size_t)b * S * CS + dir * H;
    const float* hb = con_h + (size_t)b * S * CS + dir * H;
    for (int i2 = tid; i2 < S * 100; i2 += 128) {
        int s = i2 / 100, h2 = i2 % 100;
        float2 wv = *reinterpret_cast<const float2*>(wsh + 2 * h2);
        float2 pv = *reinterpret_cast<const float2*>(pb + s * CS + 2 * h2);
        float2 hv = *reinterpret_cast<const float2*>(hb + s * CS + 2 * h2);
        pv.x *= wv.x; pv.y *= wv.y;
        hv.x *= wv.x; hv.y *= wv.y;
        *reinterpret_cast<float2*>(A  + s * HP + 2 * h2) = pv;
        *reinterpret_cast<float2*>(Bm + s * HP + 2 * h2) = hv;
    }
    __syncthreads();

    if (tid < S) {
        float acc = 0.f;
        #pragma unroll 4
        for (int k = 0; k < 100; k++) {
            float2 v = *reinterpret_cast<const float2*>(A + tid * HP + 2 * k);
            acc += v.x * v.x + v.y * v.y;
        }
        na[tid] = sqrtf(acc);
    } else {
        int q = tid - S;
        float acc = 0.f;
        #pragma unroll 4
        for (int k = 0; k < 100; k++) {
            float2 v = *reinterpret_cast<const float2*>(Bm + q * HP + 2 * k);
            acc += v.x * v.x + v.y * v.y;
        }
        nb[q] = sqrtf(acc);
    }
    __syncthreads();

    const int tx = tid & 15, ty = tid >> 4;
    const ull* Ap[8]; const ull* Bp[4];
    #pragma unroll
    for (int i = 0; i < 8; i++) Ap[i] = reinterpret_cast<const ull*>(A  + (ty + 8 * i) * HP);
    #pragma unroll
    for (int j = 0; j < 4; j++) Bp[j] = reinterpret_cast<const ull*>(Bm + (tx + 16 * j) * HP);

    ull acc2[8][4];
    #pragma unroll
    for (int i = 0; i < 8; i++)
        #pragma unroll
        for (int j = 0; j < 4; j++) acc2[i][j] = 0ull;

    ull ca[8], cb[4];
    #pragma unroll
    for (int i = 0; i < 8; i++) ca[i] = Ap[i][0];
    #pragma unroll
    for (int j = 0; j < 4; j++) cb[j] = Bp[j][0];

    #pragma unroll 2
    for (int h2 = 1; h2 < 100; h2++) {
        ull ta[8], tb[4];
        #pragma unroll
        for (int i = 0; i < 8; i++) ta[i] = Ap[i][h2];
        #pragma unroll
        for (int j = 0; j < 4; j++) tb[j] = Bp[j][h2];
        #pragma unroll
        for (int i = 0; i < 8; i++)
            #pragma unroll
            for (int j = 0; j < 4; j++) fma2(acc2[i][j], ca[i], cb[j]);
        #pragma unroll
        for (int i = 0; i < 8; i++) ca[i] = ta[i];
        #pragma unroll
        for (int j = 0; j < 4; j++) cb[j] = tb[j];
    }
    #pragma unroll
    for (int i = 0; i < 8; i++)
        #pragma unroll
        for (int j = 0; j < 4; j++) fma2(acc2[i][j], ca[i], cb[j]);

    float pmax[8], qmax[4];
    #pragma unroll
    for (int i = 0; i < 8; i++) pmax[i] = -INFINITY;
    #pragma unroll
    for (int j = 0; j < 4; j++) qmax[j] = -INFINITY;

    #pragma unroll
    for (int i = 0; i < 8; i++) {
        int p = ty + 8 * i;
        #pragma unroll
        for (int j = 0; j < 4; j++) {
            int q = tx + 16 * j;
            float d = na[p] * nb[q];
            float c = red2(acc2[i][j]) / (d > EPSV ? d : EPSV);
            pmax[i] = fmaxf(pmax[i], c);
            qmax[j] = fmaxf(qmax[j], c);
        }
    }
    #pragma unroll
    for (int i = 0; i < 8; i++) redP[(ty + 8 * i) * 16 + tx] = pmax[i];
    #pragma unroll
    for (int j = 0; j < 4; j++) redQ[(tx + 16 * j) * 8 + ty] = qmax[j];
    __syncthreads();

    const int colbase = (dir == 0 ? 20 : 100) + l;
    if (tid < S) {
        float m = -INFINITY;
        #pragma unroll
        for (int k = 0; k < 16; k++) m = fmaxf(m, redP[tid * 16 + k]);
        out[((size_t)b * S + tid) * MV + colbase] = m;                      // mv_p
    } else {
        int q = tid - S;
        float m = -INFINITY;
        #pragma unroll
        for (int k = 0; k < 8; k++) m = fmaxf(m, redQ[q * 8 + k]);
        out[(size_t)PSIZE + ((size_t)b * S + q) * MV + colbase] = m;        // mv_h
    }
}

// ================================ launcher ===================================
extern "C" void kernel_launch(void* const* d_in, const int* in_sizes, int n_in,
                              void* d_out, int out_size) {
    const float* con_p = (const float*)d_in[0];
    const float* con_h = (const float*)d_in[1];
    const float* w1 = (const float*)d_in[2];
    const float* w2 = (const float*)d_in[3];
    const float* w3 = (const float*)d_in[4];
    const float* w4 = (const float*)d_in[5];
    const float* w5 = (const float*)d_in[6];
    const float* w6 = (const float*)d_in[7];
    const float* w7 = (const float*)d_in[8];
    const float* w8 = (const float*)d_in[9];
    float* out = (float*)d_out;

    constexpr size_t SM_A1 = (size_t)(2 * S * HP + 2 * S + S * 16 + S * 8) * sizeof(float);
    constexpr size_t SM_A2 = (size_t)(2 * S * AST + S * VST + S) * sizeof(float);
    constexpr size_t SM_B  = (size_t)(2 * 32 * HP + L * WST) * sizeof(float);
    constexpr size_t SM_C  = (size_t)(2 * S * HP + 2 * S + H + S * 16 + S * 8) * sizeof(float);

    static bool attrs_set = false;
    if (!attrs_set) {
        cudaFuncSetAttribute(attn_kernel,     cudaFuncAttributeMaxDynamicSharedMemorySize, (int)SM_A1);
        cudaFuncSetAttribute(attderiv_kernel, cudaFuncAttributeMaxDynamicSharedMemorySize, (int)SM_A2);
        cudaFuncSetAttribute(match_kernel,    cudaFuncAttributeMaxDynamicSharedMemorySize, (int)SM_B);
        cudaFuncSetAttribute(pairwise_kernel, cudaFuncAttributeMaxDynamicSharedMemorySize, (int)SM_C);
        attrs_set = true;
    }

    attn_kernel<<<dim3(B, 2), 128, SM_A1>>>(con_p, con_h);
    attderiv_kernel<<<dim3(B, 2, 4), 256, SM_A2>>>(con_p, con_h);
    match_kernel<<<dim3(B, 12, 2), 128, SM_B>>>(con_p, con_h, w1, w2, w5, w6, w7, w8, out);
    pairwise_kernel<<<dim3(B, L, 2), 128, SM_C>>>(con_p, con_h, w3, w4, out);
}

// round 5
// speedup vs baseline: 3.2559x; 1.8168x over previous
#include <cuda_runtime.h>
#include <math.h>

#define EPSV 1e-8f

typedef unsigned long long ull;

namespace {
constexpr int B  = 32;
constexpr int S  = 64;
constexpr int H  = 200;
constexpr int L  = 20;
constexpr int HP = 202;      // smem row stride (even; 101 8B-units, 101%16=5 -> conflict-free)
constexpr int CS = 400;      // con_* inner stride (2*H)
constexpr int MV = 160;      // 8*L output columns
constexpr int PSIZE = B * S * MV;
constexpr int AST = 66;      // attderiv att/attT row stride
constexpr int VST = 104;     // attderiv V stride
constexpr int WST = 200;     // match W2 row stride
}

// packed f32x2 helpers (ptxas never auto-fuses these)
__device__ __forceinline__ void fma2(ull& d, ull a, ull b) {
    asm("fma.rn.f32x2 %0, %1, %2, %0;" : "+l"(d) : "l"(a), "l"(b));
}
__device__ __forceinline__ ull mul2(ull a, ull b) {
    ull r; asm("mul.rn.f32x2 %0, %1, %2;" : "=l"(r) : "l"(a), "l"(b)); return r;
}
__device__ __forceinline__ float red2(ull v) {
    float2 f = *reinterpret_cast<float2*>(&v);
    return f.x + f.y;
}

// ---------------- scratch (device globals; no allocation allowed) -------------
__device__ __align__(16) float g_att[2 * B * S * S];
__device__ __align__(16) float g_rowsum[2 * B * S];
__device__ __align__(16) float g_colsum[2 * B * S];
__device__ __align__(16) float g_amean_h[2 * B * S * H];
__device__ __align__(16) float g_amax_h [2 * B * S * H];
__device__ __align__(16) float g_amean_p[2 * B * S * H];
__device__ __align__(16) float g_amax_p [2 * B * S * H];

// ============================ Kernel A1: attention ===========================
// grid (B, 2), 256 threads, 16x16 grid, 4x4 tile, f32x2. Shuffle reductions.
__global__ void __launch_bounds__(256)
attn_kernel(const float* __restrict__ con_p,
            const float* __restrict__ con_h) {
    extern __shared__ float sm[];
    float* P     = sm;                 // S*HP
    float* Hm    = P  + S * HP;        // S*HP
    float* np    = Hm + S * HP;        // S
    float* nh    = np + S;             // S
    float* redCS = nh + S;             // S*8

    const int b = blockIdx.x, dir = blockIdx.y;
    const int tid = threadIdx.x;
    const float* pbase = con_p + (size_t)b * S * CS + dir * H;
    const float* hbase = con_h + (size_t)b * S * CS + dir * H;

    for (int i2 = tid; i2 < S * 100; i2 += 256) {
        int s = i2 / 100, h2 = i2 % 100;
        *reinterpret_cast<float2*>(P  + s * HP + 2 * h2) =
            *reinterpret_cast<const float2*>(pbase + s * CS + 2 * h2);
        *reinterpret_cast<float2*>(Hm + s * HP + 2 * h2) =
            *reinterpret_cast<const float2*>(hbase + s * CS + 2 * h2);
    }
    __syncthreads();

    if (tid < 64) {
        float acc = 0.f;
        #pragma unroll 4
        for (int k = 0; k < 100; k++) {
            float2 v = *reinterpret_cast<const float2*>(P + tid * HP + 2 * k);
            acc += v.x * v.x + v.y * v.y;
        }
        np[tid] = sqrtf(acc);
    } else if (tid < 128) {
        int q = tid - 64;
        float acc = 0.f;
        #pragma unroll 4
        for (int k = 0; k < 100; k++) {
            float2 v = *reinterpret_cast<const float2*>(Hm + q * HP + 2 * k);
            acc += v.x * v.x + v.y * v.y;
        }
        nh[q] = sqrtf(acc);
    }
    __syncthreads();

    const int tx = tid & 15, ty = tid >> 4;
    const int lane = tid & 31, warp = tid >> 5;
    const ull* Ap[4]; const ull* Bp[4];
    #pragma unroll
    for (int i = 0; i < 4; i++) Ap[i] = reinterpret_cast<const ull*>(P  + (ty + 16 * i) * HP);
    #pragma unroll
    for (int j = 0; j < 4; j++) Bp[j] = reinterpret_cast<const ull*>(Hm + (tx + 16 * j) * HP);

    ull acc2[4][4];
    #pragma unroll
    for (int i = 0; i < 4; i++)
        #pragma unroll
        for (int j = 0; j < 4; j++) acc2[i][j] = 0ull;

    ull ca[4], cb[4];
    #pragma unroll
    for (int i = 0; i < 4; i++) ca[i] = Ap[i][0];
    #pragma unroll
    for (int j = 0; j < 4; j++) cb[j] = Bp[j][0];

    #pragma unroll 2
    for (int h2 = 1; h2 < 100; h2++) {
        ull ta[4], tb[4];
        #pragma unroll
        for (int i = 0; i < 4; i++) ta[i] = Ap[i][h2];
        #pragma unroll
        for (int j = 0; j < 4; j++) tb[j] = Bp[j][h2];
        #pragma unroll
        for (int i = 0; i < 4; i++)
            #pragma unroll
            for (int j = 0; j < 4; j++) fma2(acc2[i][j], ca[i], cb[j]);
        #pragma unroll
        for (int i = 0; i < 4; i++) ca[i] = ta[i];
        #pragma unroll
        for (int j = 0; j < 4; j++) cb[j] = tb[j];
    }
    #pragma unroll
    for (int i = 0; i < 4; i++)
        #pragma unroll
        for (int j = 0; j < 4; j++) fma2(acc2[i][j], ca[i], cb[j]);

    float* gatt = g_att + (size_t)(dir * B + b) * S * S;
    float rsum[4], csum[4];
    #pragma unroll
    for (int i = 0; i < 4; i++) rsum[i] = 0.f;
    #pragma unroll
    for (int j = 0; j < 4; j++) csum[j] = 0.f;

    #pragma unroll
    for (int i = 0; i < 4; i++) {
        int p = ty + 16 * i;
        #pragma unroll
        for (int j = 0; j < 4; j++) {
            int q = tx + 16 * j;
            float d = np[p] * nh[q];
            float c = red2(acc2[i][j]) / (d > EPSV ? d : EPSV);
            gatt[p * S + q] = c;
            rsum[i] += c;
            csum[j] += c;
        }
    }
    // row sums: reduce over tx (16-lane groups), lanes 0/16 own rows
    #pragma unroll
    for (int m = 1; m <= 8; m <<= 1)
        #pragma unroll
        for (int i = 0; i < 4; i++)
            rsum[i] += __shfl_xor_sync(0xffffffffu, rsum[i], m);
    if (tx == 0) {
        #pragma unroll
        for (int i = 0; i < 4; i++)
            g_rowsum[(dir * B + b) * S + (ty + 16 * i)] = rsum[i];
    }
    // col sums: combine the two ty's in-warp, then cross-warp via smem
    #pragma unroll
    for (int j = 0; j < 4; j++)
        csum[j] += __shfl_xor_sync(0xffffffffu, csum[j], 16);
    if (lane < 16) {
        #pragma unroll
        for (int j = 0; j < 4; j++)
            redCS[(tx + 16 * j) * 8 + warp] = csum[j];
    }
    __syncthreads();
    if (tid < 64) {
        float s0 = 0.f;
        #pragma unroll
        for (int k = 0; k < 8; k++) s0 += redCS[tid * 8 + k];
        g_colsum[(dir * B + b) * S + tid] = s0;
    }
}

// ===================== Kernel A2: att mean/max vectors =======================
__global__ void __launch_bounds__(256)
attderiv_kernel(const float* __restrict__ con_p,
                const float* __restrict__ con_h) {
    extern __shared__ float sm[];
    float* att  = sm;                    // S*AST
    float* attT = att + S * AST;         // S*AST
    float* V    = attT + S * AST;        // S*VST
    float* dsum = V + S * VST;           // S

    const int b = blockIdx.x, dir = blockIdx.y;
    const int side = blockIdx.z >> 1;
    const int ck = blockIdx.z & 1;
    const int h0 = ck * 100;
    const int tid = threadIdx.x;

    const float* gatt = g_att + (size_t)(dir * B + b) * S * S;
    for (int i = tid; i < S * S; i += 256) {
        int p = i >> 6, q = i & 63;
        float v = gatt[i];
        att [p * AST + q] = v;
        attT[q * AST + p] = v;
    }

    const float* src = (side == 0 ? con_h : con_p) + (size_t)b * S * CS + dir * H + h0;
    for (int i4 = tid; i4 < S * 25; i4 += 256) {
        int s = i4 / 25, c4 = i4 % 25;
        *reinterpret_cast<float4*>(V + s * VST + c4 * 4) =
            *reinterpret_cast<const float4*>(src + s * CS + c4 * 4);
    }
    if (tid < S)
        dsum[tid] = (side == 0 ? g_rowsum : g_colsum)[(dir * B + b) * S + tid];
    __syncthreads();

    float* gmean = (side == 0 ? g_amean_h : g_amean_p) + (size_t)(dir * B + b) * S * H + h0;
    float* gmax  = (side == 0 ? g_amax_h  : g_amax_p ) + (size_t)(dir * B + b) * S * H + h0;

    if (tid < 200) {
        const int oi = tid / 25, hi = tid % 25;
        const int o0 = oi * 8, hb = hi * 4;
        const float* M = (side == 0) ? att : attT;   // M[o][q]

        float ss[8][4], sx[8][4];
        #pragma unroll
        for (int io = 0; io < 8; io++)
            #pragma unroll
            for (int k = 0; k < 4; k++) { ss[io][k] = 0.f; sx[io][k] = -INFINITY; }

        for (int q2 = 0; q2 < 32; q2++) {
            const int q = 2 * q2;
            float2 av[8];
            #pragma unroll
            for (int io = 0; io < 8; io++)
                av[io] = *reinterpret_cast<const float2*>(M + (o0 + io) * AST + q);
            float4 v0 = *reinterpret_cast<const float4*>(V + q * VST + hb);
            float4 v1 = *reinterpret_cast<const float4*>(V + (q + 1) * VST + hb);
            float vv0[4] = {v0.x, v0.y, v0.z, v0.w};
            float vv1[4] = {v1.x, v1.y, v1.z, v1.w};
            #pragma unroll
            for (int io = 0; io < 8; io++) {
                float ax = av[io].x, ay = av[io].y;
                #pragma unroll
                for (int k = 0; k < 4; k++) {
                    float t0 = ax * vv0[k];
                    float t1 = ay * vv1[k];
                    ss[io][k] += t0 + t1;
                    sx[io][k] = fmaxf(sx[io][k], fmaxf(t0, t1));
                }
            }
        }
        #pragma unroll
        for (int io = 0; io < 8; io++) {
            float d = dsum[o0 + io];
            float inv = 1.f / (d > EPSV ? d : EPSV);
            float4 m4, x4;
            m4.x = ss[io][0] * inv; m4.y = ss[io][1] * inv;
            m4.z = ss[io][2] * inv; m4.w = ss[io][3] * inv;
            x4.x = sx[io][0]; x4.y = sx[io][1]; x4.z = sx[io][2]; x4.w = sx[io][3];
            *reinterpret_cast<float4*>(gmean + (o0 + io) * H + hb) = m4;
            *reinterpret_cast<float4*>(gmax  + (o0 + io) * H + hb) = x4;
        }
    }
}

// ====================== Kernel B: 12 fused mp_match ops ======================
__global__ void __launch_bounds__(128)
match_kernel(const float* __restrict__ con_p,
             const float* __restrict__ con_h,
             const float* __restrict__ w1, const float* __restrict__ w2,
             const float* __restrict__ w5, const float* __restrict__ w6,
             const float* __restrict__ w7, const float* __restrict__ w8,
             float* __restrict__ out) {
    extern __shared__ float sm[];
    float* V1 = sm;                 // 32*HP
    float* V2 = V1 + 32 * HP;       // 32*HP (kind 0 uses row 0 only)
    float* W2 = V2 + 32 * HP;       // L*WST

    const int b = blockIdx.x, op = blockIdx.y, shalf = blockIdx.z;
    const int side = op / 6;
    const int r = op % 6;
    const int kind = r >> 1;
    const int dir = r & 1;
    const int tid = threadIdx.x;
    const int s0 = shalf * 32;

    const float* v1 = (side == 0 ? con_p : con_h) + (size_t)b * S * CS + dir * H;
    for (int i2 = tid; i2 < 32 * 100; i2 += 128) {
        int s = i2 / 100, h2 = i2 % 100;
        *reinterpret_cast<float2*>(V1 + s * HP + 2 * h2) =
            *reinterpret_cast<const float2*>(v1 + (s0 + s) * CS + 2 * h2);
    }

    if (kind == 0) {
        const float* v2 = (side == 0 ? con_h : con_p)
                        + (size_t)b * S * CS + (dir == 0 ? (S - 1) : 0) * CS + dir * H;
        for (int h2 = tid; h2 < 100; h2 += 128)
            *reinterpret_cast<float2*>(V2 + 2 * h2) =
                *reinterpret_cast<const float2*>(v2 + 2 * h2);
    } else {
        const float* v2 = (kind == 1 ? (side == 0 ? g_amean_h : g_amean_p)
                                     : (side == 0 ? g_amax_h  : g_amax_p))
                        + (size_t)(dir * B + b) * S * H;
        for (int i2 = tid; i2 < 32 * 100; i2 += 128) {
            int s = i2 / 100, h2 = i2 % 100;
            *reinterpret_cast<float2*>(V2 + s * HP + 2 * h2) =
                *reinterpret_cast<const float2*>(v2 + (s0 + s) * H + 2 * h2);
        }
    }

    const float* w = (kind == 0 ? (dir == 0 ? w1 : w2)
                   : kind == 1 ? (dir == 0 ? w5 : w6)
                               : (dir == 0 ? w7 : w8));
    for (int i2 = tid; i2 < L * 100; i2 += 128) {
        int l = i2 / 100, h2 = i2 % 100;
        float2 wv = *reinterpret_cast<const float2*>(w + l * H + 2 * h2);
        float2 sq; sq.x = wv.x * wv.x; sq.y = wv.y * wv.y;
        *reinterpret_cast<float2*>(W2 + l * WST + 2 * h2) = sq;
    }
    __syncthreads();

    const int tx = tid & 3;        // l group: l = tx*5 + il
    const int ty = tid >> 2;       // s = s0 + ty

    const ull* Ap = reinterpret_cast<const ull*>(V1 + ty * HP);
    const ull* Bp = reinterpret_cast<const ull*>((kind == 0) ? V2 : V2 + ty * HP);
    const ull* Wp[5];
    #pragma unroll
    for (int il = 0; il < 5; il++)
        Wp[il] = reinterpret_cast<const ull*>(W2 + (tx * 5 + il) * WST);

    ull dacc[5], naa[5], nbb[5];
    #pragma unroll
    for (int il = 0; il < 5; il++) { dacc[il] = 0ull; naa[il] = 0ull; nbb[il] = 0ull; }

    #pragma unroll 2
    for (int h2 = 0; h2 < 100; h2++) {
        ull a = Ap[h2], bb = Bp[h2];
        ull u1 = mul2(a, bb), u2 = mul2(a, a), u3 = mul2(bb, bb);
        #pragma unroll
        for (int il = 0; il < 5; il++) {
            ull wv = Wp[il][h2];
            fma2(dacc[il], u1, wv);
            fma2(naa[il], u2, wv);
            fma2(nbb[il], u3, wv);
        }
    }

    const int col = (kind == 0 ? 0 : kind == 1 ? 40 : 60) + dir * 80;
    float* obase = out + (size_t)side * PSIZE + (size_t)b * S * MV;
    #pragma unroll
    for (int il = 0; il < 5; il++) {
        float d = sqrtf(red2(naa[il])) * sqrtf(red2(nbb[il]));
        obase[(s0 + ty) * MV + col + (tx * 5 + il)] = red2(dacc[il]) / fmaxf(d, EPSV);
    }
}

// ================= Kernel C: pairwise mp + max reductions ====================
// grid (B, L, 2), 256 threads, 16x16 grid, 4x4 tile, shuffle reductions.
__global__ void __launch_bounds__(256)
pairwise_kernel(const float* __restrict__ con_p,
                const float* __restrict__ con_h,
                const float* __restrict__ w3,
                const float* __restrict__ w4,
                float* __restrict__ out) {
    extern __shared__ float sm[];
    float* A    = sm;                 // S*HP  (p * w_l)
    float* Bm   = A + S * HP;         // S*HP  (h * w_l)
    float* na   = Bm + S * HP;        // S
    float* nb   = na + S;             // S
    float* wsh  = nb + S;             // H
    float* redQ = wsh + H;            // S*8

    const int b = blockIdx.x, l = blockIdx.y, dir = blockIdx.z;
    const int tid = threadIdx.x;

    const float* w = (dir == 0 ? w3 : w4) + l * H;
    for (int h2 = tid; h2 < 100; h2 += 256)
        *reinterpret_cast<float2*>(wsh + 2 * h2) =
            *reinterpret_cast<const float2*>(w + 2 * h2);
    __syncthreads();

    const float* pb = con_p + (size_t)b * S * CS + dir * H;
    const float* hb = con_h + (size_t)b * S * CS + dir * H;
    for (int i2 = tid; i2 < S * 100; i2 += 256) {
        int s = i2 / 100, h2 = i2 % 100;
        float2 wv = *reinterpret_cast<const float2*>(wsh + 2 * h2);
        float2 pv = *reinterpret_cast<const float2*>(pb + s * CS + 2 * h2);
        float2 hv = *reinterpret_cast<const float2*>(hb + s * CS + 2 * h2);
        pv.x *= wv.x; pv.y *= wv.y;
        hv.x *= wv.x; hv.y *= wv.y;
        *reinterpret_cast<float2*>(A  + s * HP + 2 * h2) = pv;
        *reinterpret_cast<float2*>(Bm + s * HP + 2 * h2) = hv;
    }
    __syncthreads();

    if (tid < 64) {
        float acc = 0.f;
        #pragma unroll 4
        for (int k = 0; k < 100; k++) {
            float2 v = *reinterpret_cast<const float2*>(A + tid * HP + 2 * k);
            acc += v.x * v.x + v.y * v.y;
        }
        na[tid] = sqrtf(acc);
    } else if (tid < 128) {
        int q = tid - 64;
        float acc = 0.f;
        #pragma unroll 4
        for (int k = 0; k < 100; k++) {
            float2 v = *reinterpret_cast<const float2*>(Bm + q * HP + 2 * k);
            acc += v.x * v.x + v.y * v.y;
        }
        nb[q] = sqrtf(acc);
    }
    __syncthreads();

    const int tx = tid & 15, ty = tid >> 4;
    const int lane = tid & 31, warp = tid >> 5;
    const ull* Ap[4]; const ull* Bp[4];
    #pragma unroll
    for (int i = 0; i < 4; i++) Ap[i] = reinterpret_cast<const ull*>(A  + (ty + 16 * i) * HP);
    #pragma unroll
    for (int j = 0; j < 4; j++) Bp[j] = reinterpret_cast<const ull*>(Bm + (tx + 16 * j) * HP);

    ull acc2[4][4];
    #pragma unroll
    for (int i = 0; i < 4; i++)
        #pragma unroll
        for (int j = 0; j < 4; j++) acc2[i][j] = 0ull;

    ull ca[4], cb[4];
    #pragma unroll
    for (int i = 0; i < 4; i++) ca[i] = Ap[i][0];
    #pragma unroll
    for (int j = 0; j < 4; j++) cb[j] = Bp[j][0];

    #pragma unroll 2
    for (int h2 = 1; h2 < 100; h2++) {
        ull ta[4], tb[4];
        #pragma unroll
        for (int i = 0; i < 4; i++) ta[i] = Ap[i][h2];
        #pragma unroll
        for (int j = 0; j < 4; j++) tb[j] = Bp[j][h2];
        #pragma unroll
        for (int i = 0; i < 4; i++)
            #pragma unroll
            for (int j = 0; j < 4; j++) fma2(acc2[i][j], ca[i], cb[j]);
        #pragma unroll
        for (int i = 0; i < 4; i++) ca[i] = ta[i];
        #pragma unroll
        for (int j = 0; j < 4; j++) cb[j] = tb[j];
    }
    #pragma unroll
    for (int i = 0; i < 4; i++)
        #pragma unroll
        for (int j = 0; j < 4; j++) fma2(acc2[i][j], ca[i], cb[j]);

    float pmax[4], qmax[4];
    #pragma unroll
    for (int i = 0; i < 4; i++) pmax[i] = -INFINITY;
    #pragma unroll
    for (int j = 0; j < 4; j++) qmax[j] = -INFINITY;

    #pragma unroll
    for (int i = 0; i < 4; i++) {
        int p = ty + 16 * i;
        #pragma unroll
        for (int j = 0; j < 4; j++) {
            int q = tx + 16 * j;
            float d = na[p] * nb[q];
            float c = red2(acc2[i][j]) / (d > EPSV ? d : EPSV);
            pmax[i] = fmaxf(pmax[i], c);
            qmax[j] = fmaxf(qmax[j], c);
        }
    }

    const int colbase = (dir == 0 ? 20 : 100) + l;
    // row max: reduce over tx within 16-lane groups; lanes with tx==0 write
    #pragma unroll
    for (int m = 1; m <= 8; m <<= 1)
        #pragma unroll
        for (int i = 0; i < 4; i++)
            pmax[i] = fmaxf(pmax[i], __shfl_xor_sync(0xffffffffu, pmax[i], m));
    if (tx == 0) {
        #pragma unroll
        for (int i = 0; i < 4; i++)
            out[((size_t)b * S + (ty + 16 * i)) * MV + colbase] = pmax[i];   // mv_p
    }
    // col max: combine two ty's in-warp, then cross-warp via smem
    #pragma unroll
    for (int j = 0; j < 4; j++)
        qmax[j] = fmaxf(qmax[j], __shfl_xor_sync(0xffffffffu, qmax[j], 16));
    if (lane < 16) {
        #pragma unroll
        for (int j = 0; j < 4; j++)
            redQ[(tx + 16 * j) * 8 + warp] = qmax[j];
    }
    __syncthreads();
    if (tid < 64) {
        float m = -INFINITY;
        #pragma unroll
        for (int k = 0; k < 8; k++) m = fmaxf(m, redQ[tid * 8 + k]);
        out[(size_t)PSIZE + ((size_t)b * S + tid) * MV + colbase] = m;       // mv_h
    }
}

// ================================ launcher ===================================
extern "C" void kernel_launch(void* const* d_in, const int* in_sizes, int n_in,
                              void* d_out, int out_size) {
    const float* con_p = (const float*)d_in[0];
    const float* con_h = (const float*)d_in[1];
    const float* w1 = (const float*)d_in[2];
    const float* w2 = (const float*)d_in[3];
    const float* w3 = (const float*)d_in[4];
    const float* w4 = (const float*)d_in[5];
    const float* w5 = (const float*)d_in[6];
    const float* w6 = (const float*)d_in[7];
    const float* w7 = (const float*)d_in[8];
    const float* w8 = (const float*)d_in[9];
    float* out = (float*)d_out;

    constexpr size_t SM_A1 = (size_t)(2 * S * HP + 2 * S + S * 8) * sizeof(float);
    constexpr size_t SM_A2 = (size_t)(2 * S * AST + S * VST + S) * sizeof(float);
    constexpr size_t SM_B  = (size_t)(2 * 32 * HP + L * WST) * sizeof(float);
    constexpr size_t SM_C  = (size_t)(2 * S * HP + 2 * S + H + S * 8) * sizeof(float);

    // One-time setup at first (non-capture, correctness) call: attributes,
    // side stream and fork/join events. Only launches happen during capture.
    static cudaStream_t s2 = nullptr;
    static cudaEvent_t evFork = nullptr, evJoin = nullptr;
    static bool init_done = false;
    if (!init_done) {
        cudaFuncSetAttribute(attn_kernel,     cudaFuncAttributeMaxDynamicSharedMemorySize, (int)SM_A1);
        cudaFuncSetAttribute(attderiv_kernel, cudaFuncAttributeMaxDynamicSharedMemorySize, (int)SM_A2);
        cudaFuncSetAttribute(match_kernel,    cudaFuncAttributeMaxDynamicSharedMemorySize, (int)SM_B);
        cudaFuncSetAttribute(pairwise_kernel, cudaFuncAttributeMaxDynamicSharedMemorySize, (int)SM_C);
        cudaStreamCreateWithFlags(&s2, cudaStreamNonBlocking);
        cudaEventCreateWithFlags(&evFork, cudaEventDisableTiming);
        cudaEventCreateWithFlags(&evJoin, cudaEventDisableTiming);
        init_done = true;
    }

    // Fork: pairwise (independent; writes out cols 20-39/100-119) on s2,
    // attn -> attderiv -> match chain on the main stream. Join at the end.
    cudaEventRecord(evFork, 0);
    cudaStreamWaitEvent(s2, evFork, 0);
    pairwise_kernel<<<dim3(B, L, 2), 256, SM_C, s2>>>(con_p, con_h, w3, w4, out);

    attn_kernel<<<dim3(B, 2), 256, SM_A1>>>(con_p, con_h);
    attderiv_kernel<<<dim3(B, 2, 4), 256, SM_A2>>>(con_p, con_h);
    match_kernel<<<dim3(B, 12, 2), 128, SM_B>>>(con_p, con_h, w1, w2, w5, w6, w7, w8, out);

    cudaEventRecord(evJoin, s2);
    cudaStreamWaitEvent(0, evJoin, 0);
}